// round 2
// baseline (speedup 1.0000x reference)
#include <cuda_runtime.h>

// Problem constants (fixed shapes per setup_inputs)
#define B_  4
#define N_  20000
#define DN_ 64
#define DM_ 128
#define E_  160000
#define L_  2
#define BN3 384   // 3 * DM

// ---------------- device scratch (no allocations allowed) ----------------
__device__ float g_HW[(size_t)B_ * N_ * BN3];   // per-relation transformed nodes, [B,N,3*128]
__device__ float g_eagg[(size_t)N_ * DM_];      // per-node edge-term aggregate (batch independent)
__device__ float g_S[2 * N_ * 16];              // per-node sum of edge attrs per relation
__device__ int   g_deg[3 * N_];
__device__ int   g_off[3 * N_];
__device__ int   g_cur[3 * N_];
__device__ int   g_csr[3 * E_];                 // src node ids grouped by dst

// ---------------- CSR build ----------------
__global__ void k_zero() {
    int i = blockIdx.x * blockDim.x + threadIdx.x;
    if (i < 3 * N_) g_deg[i] = 0;
    if (i < 2 * N_ * 16) g_S[i] = 0.f;
}

__global__ void k_count(const int* __restrict__ e0, const int* __restrict__ e1,
                        const int* __restrict__ e2) {
    int t = blockIdx.x * blockDim.x + threadIdx.x;
    if (t >= 3 * E_) return;
    int r = t / E_, e = t - r * E_;
    const int* ei = (r == 0) ? e0 : (r == 1) ? e1 : e2;
    int dst = ei[E_ + e];
    atomicAdd(&g_deg[r * N_ + dst], 1);
}

// one block per relation: exclusive scan of deg -> off (and cursor copy)
__global__ void k_scan() {
    __shared__ int sh[1024];
    int r = blockIdx.x;
    int t = threadIdx.x;
    const int CH = 20;  // 1024*20 >= 20000
    int base = t * CH;
    int part = 0;
    for (int i = 0; i < CH; ++i) {
        int idx = base + i;
        if (idx < N_) part += g_deg[r * N_ + idx];
    }
    sh[t] = part;
    __syncthreads();
    for (int o = 1; o < 1024; o <<= 1) {
        int v = (t >= o) ? sh[t - o] : 0;
        __syncthreads();
        sh[t] += v;
        __syncthreads();
    }
    int run = (t > 0) ? sh[t - 1] : 0;
    for (int i = 0; i < CH; ++i) {
        int idx = base + i;
        if (idx < N_) {
            g_off[r * N_ + idx] = run;
            g_cur[r * N_ + idx] = run;
            run += g_deg[r * N_ + idx];
        }
    }
}

__global__ void k_fill(const int* __restrict__ e0, const int* __restrict__ e1,
                       const int* __restrict__ e2) {
    int t = blockIdx.x * blockDim.x + threadIdx.x;
    if (t >= 3 * E_) return;
    int r = t / E_, e = t - r * E_;
    const int* ei = (r == 0) ? e0 : (r == 1) ? e1 : e2;
    int src = ei[e];
    int dst = ei[E_ + e];
    int pos = atomicAdd(&g_cur[r * N_ + dst], 1);
    g_csr[r * E_ + pos] = src;
}

// S_r[n,k] = sum over edges (dst==n) of ea_r[e,k]
__global__ void k_scatS(const float* __restrict__ ea0, const float* __restrict__ ea1,
                        const int* __restrict__ e0, const int* __restrict__ e1) {
    int t = blockIdx.x * blockDim.x + threadIdx.x;
    if (t >= 2 * E_) return;
    int r = t / E_, e = t - r * E_;
    const int* ei = r ? e1 : e0;
    const float* ea = r ? ea1 : ea0;
    int dst = ei[E_ + e];
    float* srow = &g_S[(r * N_ + dst) * 16];
    const float* arow = &ea[e * 16];
#pragma unroll
    for (int k = 0; k < 16; ++k) atomicAdd(&srow[k], arow[k]);
}

// ---------------- fp32 SGEMM: C[M x (gridDim.y*128)] = A[M x K] @ B tiles ----------------
// BM=BN=128, BK=32, 256 threads, 8x8 micro-tile
__global__ __launch_bounds__(256, 2) void k_sgemm(
    const float* __restrict__ A, const float* __restrict__ Bbase, long strideB,
    const float* __restrict__ biasBase, int strideBias,
    float* __restrict__ C, int K, int ldC) {
    __shared__ float As[32 * 129];
    __shared__ float Bs[32 * 128];

    const float* Bt = Bbase + (long)blockIdx.y * strideB;
    const float* bias = biasBase + (long)blockIdx.y * strideBias;
    const int row0 = blockIdx.x * 128;
    const int tid = threadIdx.x;
    const int tx = tid & 15;       // col micro-tile
    const int ty = tid >> 4;       // row micro-tile

    float acc[8][8];
#pragma unroll
    for (int i = 0; i < 8; ++i)
#pragma unroll
        for (int j = 0; j < 8; ++j) acc[i][j] = 0.f;

    for (int kc = 0; kc < K; kc += 32) {
        // load A tile [128 rows x 32 k], transposed into As[kk][row]
#pragma unroll
        for (int t = 0; t < 4; ++t) {
            int f = tid + t * 256;          // float4 id in [0,1024)
            int r = f >> 3;                 // row 0..127
            int kk4 = (f & 7) << 2;         // k within chunk
            float4 v = *(const float4*)&A[(size_t)(row0 + r) * K + kc + kk4];
            As[(kk4 + 0) * 129 + r] = v.x;
            As[(kk4 + 1) * 129 + r] = v.y;
            As[(kk4 + 2) * 129 + r] = v.z;
            As[(kk4 + 3) * 129 + r] = v.w;
        }
        // load B tile [32 k x 128 cols]
#pragma unroll
        for (int t = 0; t < 4; ++t) {
            int f = tid + t * 256;
            int kk = f >> 5;
            int c4 = (f & 31) << 2;
            float4 v = *(const float4*)&Bt[(size_t)(kc + kk) * 128 + c4];
            *(float4*)&Bs[kk * 128 + c4] = v;
        }
        __syncthreads();

#pragma unroll 2
        for (int kk = 0; kk < 32; ++kk) {
            float a[8], bf[8];
#pragma unroll
            for (int i = 0; i < 8; ++i) a[i] = As[kk * 129 + ty * 8 + i];
            float4 b0 = *(const float4*)&Bs[kk * 128 + tx * 8];
            float4 b1 = *(const float4*)&Bs[kk * 128 + tx * 8 + 4];
            bf[0] = b0.x; bf[1] = b0.y; bf[2] = b0.z; bf[3] = b0.w;
            bf[4] = b1.x; bf[5] = b1.y; bf[6] = b1.z; bf[7] = b1.w;
#pragma unroll
            for (int i = 0; i < 8; ++i)
#pragma unroll
                for (int j = 0; j < 8; ++j)
                    acc[i][j] = fmaf(a[i], bf[j], acc[i][j]);
        }
        __syncthreads();
    }

    // epilogue: += bias, write
    float4 bv0 = *(const float4*)&bias[tx * 8];
    float4 bv1 = *(const float4*)&bias[tx * 8 + 4];
    const int colBase = blockIdx.y * 128 + tx * 8;
#pragma unroll
    for (int i = 0; i < 8; ++i) {
        size_t o = (size_t)(row0 + ty * 8 + i) * ldC + colBase;
        float4 o0, o1;
        o0.x = acc[i][0] + bv0.x; o0.y = acc[i][1] + bv0.y;
        o0.z = acc[i][2] + bv0.z; o0.w = acc[i][3] + bv0.w;
        o1.x = acc[i][4] + bv1.x; o1.y = acc[i][5] + bv1.y;
        o1.z = acc[i][6] + bv1.z; o1.w = acc[i][7] + bv1.w;
        *(float4*)&C[o] = o0;
        *(float4*)&C[o + 4] = o1;
    }
}

// ---------------- per-layer edge-term aggregate ----------------
// eagg[n,j] = sum_{r<2} ( S_r[n,:] @ edge_W[l,r,:,j] + deg_r[n]*edge_b[l,r,j] )
__global__ void k_eagg(const float* __restrict__ edge_W, const float* __restrict__ edge_b, int l) {
    int n = blockIdx.x;
    int j = threadIdx.x;   // 128
    __shared__ float s0[16], s1[16];
    if (j < 16) s0[j] = g_S[(0 * N_ + n) * 16 + j];
    else if (j < 32) s1[j - 16] = g_S[(1 * N_ + n) * 16 + (j - 16)];
    __syncthreads();

    const float* W0 = edge_W + (size_t)(l * 2 + 0) * 16 * 128;
    const float* W1 = edge_W + (size_t)(l * 2 + 1) * 16 * 128;
    float d0 = (float)g_deg[0 * N_ + n];
    float d1 = (float)g_deg[1 * N_ + n];
    float acc = d0 * edge_b[(l * 2 + 0) * 128 + j] + d1 * edge_b[(l * 2 + 1) * 128 + j];
#pragma unroll
    for (int k = 0; k < 16; ++k) acc = fmaf(s0[k], W0[k * 128 + j], acc);
#pragma unroll
    for (int k = 0; k < 16; ++k) acc = fmaf(s1[k], W1[k * 128 + j], acc);
    g_eagg[(size_t)n * 128 + j] = acc;
}

// ---------------- fused gather-aggregate + relu + residual + LayerNorm ----------------
// one warp per (b,n) row; lane owns 4 columns
__global__ __launch_bounds__(256) void k_agg_ln(float* __restrict__ H,
                                                const float* __restrict__ gamma,
                                                const float* __restrict__ beta) {
    int warp = (blockIdx.x * blockDim.x + threadIdx.x) >> 5;
    int lane = threadIdx.x & 31;
    if (warp >= B_ * N_) return;
    int b = warp / N_;
    int n = warp - b * N_;
    int j4 = lane * 4;

    float4 acc = *(const float4*)&g_eagg[(size_t)n * 128 + j4];
    const size_t hwBatch = (size_t)b * N_ * BN3;

#pragma unroll
    for (int r = 0; r < 3; ++r) {
        int beg = g_off[r * N_ + n];
        int end = beg + g_deg[r * N_ + n];
        const int* __restrict__ srcs = &g_csr[r * E_];
        const int colOff = r * 128 + j4;
        for (int i = beg; i < end; ++i) {
            int s = srcs[i];
            float4 v = *(const float4*)&g_HW[hwBatch + (size_t)s * BN3 + colOff];
            acc.x += v.x; acc.y += v.y; acc.z += v.z; acc.w += v.w;
        }
    }
    // relu(agg)
    acc.x = fmaxf(acc.x, 0.f);
    acc.y = fmaxf(acc.y, 0.f);
    acc.z = fmaxf(acc.z, 0.f);
    acc.w = fmaxf(acc.w, 0.f);

    size_t hIdx = ((size_t)b * N_ + n) * 128 + j4;
    float4 h = *(const float4*)&H[hIdx];
    float x0 = h.x + acc.x, x1 = h.y + acc.y, x2 = h.z + acc.z, x3 = h.w + acc.w;

    float s = x0 + x1 + x2 + x3;
    float s2 = x0 * x0 + x1 * x1 + x2 * x2 + x3 * x3;
#pragma unroll
    for (int o = 16; o > 0; o >>= 1) {
        s += __shfl_xor_sync(0xffffffffu, s, o);
        s2 += __shfl_xor_sync(0xffffffffu, s2, o);
    }
    float mu = s * (1.f / 128.f);
    float var = s2 * (1.f / 128.f) - mu * mu;
    float inv = rsqrtf(var + 1e-5f);

    float4 g = *(const float4*)&gamma[j4];
    float4 bb = *(const float4*)&beta[j4];
    float4 out;
    out.x = (x0 - mu) * inv * g.x + bb.x;
    out.y = (x1 - mu) * inv * g.y + bb.y;
    out.z = (x2 - mu) * inv * g.z + bb.z;
    out.w = (x3 - mu) * inv * g.w + bb.w;
    *(float4*)&H[hIdx] = out;
}

// ---------------- launch ----------------
extern "C" void kernel_launch(void* const* d_in, const int* in_sizes, int n_in,
                              void* d_out, int out_size) {
    const float* node_feat = (const float*)d_in[0];
    const float* in_W      = (const float*)d_in[1];
    const float* in_b      = (const float*)d_in[2];
    const float* node_W    = (const float*)d_in[3];
    const float* node_b    = (const float*)d_in[4];
    const float* edge_W    = (const float*)d_in[5];
    const float* edge_b    = (const float*)d_in[6];
    const float* ln_g      = (const float*)d_in[7];
    const float* ln_b      = (const float*)d_in[8];
    const float* ea0       = (const float*)d_in[9];
    const float* ea1       = (const float*)d_in[10];
    const int*   e0        = (const int*)d_in[11];
    const int*   e1        = (const int*)d_in[12];
    const int*   e2        = (const int*)d_in[13];
    float* H = (float*)d_out;

    float* hw = nullptr;
    cudaGetSymbolAddress((void**)&hw, g_HW);

    // one-time (per call) index structures
    k_zero<<<2500, 256>>>();
    k_count<<<(3 * E_ + 255) / 256, 256>>>(e0, e1, e2);
    k_scan<<<3, 1024>>>();
    k_fill<<<(3 * E_ + 255) / 256, 256>>>(e0, e1, e2);
    k_scatS<<<(2 * E_ + 255) / 256, 256>>>(ea0, ea1, e0, e1);

    // input projection: H = node_feat @ in_W + in_b   [80000 x 64] @ [64 x 128]
    k_sgemm<<<dim3(625, 1), 256>>>(node_feat, in_W, 0L, in_b, 0, H, DN_, DM_);

    for (int l = 0; l < L_; ++l) {
        // HW[:, r*128:(r+1)*128] = H @ node_W[l,r] + node_b[l,r]
        k_sgemm<<<dim3(625, 3), 256>>>(H,
                                       node_W + (size_t)l * 3 * DM_ * DM_,
                                       (long)DM_ * DM_,
                                       node_b + (size_t)l * 3 * DM_,
                                       DM_,
                                       hw, DM_, BN3);
        k_eagg<<<N_, 128>>>(edge_W, edge_b, l);
        k_agg_ln<<<(B_ * N_ * 32 + 255) / 256, 256>>>(H, ln_g + l * DM_, ln_b + l * DM_);
    }
}